// round 12
// baseline (speedup 1.0000x reference)
#include <cuda_runtime.h>
#include <math.h>
#include <stdint.h>

// InstanceAwarePointMatching — memset + fused tile kernel + col merge.
//   score = exp(msm) [P,R,S]; row top-3 along s; col top-3 along r.
//   score_map = 0.5*(ref+src); corr_map = (row_hit|col_hit) & refm & srcm.
// Masks arrive as 4-byte elements (uint32 != 0).
//
// fused_tile: block per (p, 32-row chunk). 34.8KB smem -> 6 CTAs/SM (vs 3 at
// CH=64) so cp.async load phases of some blocks overlap compute of others.
// Tile -> smem via cp.async (8x16B per thread, zero staging registers).
// Row top-3 finalized in-tile (8 lanes/row, LDS.128 + max4 prefilter);
// col partial top-4 (4-row groups). Row results: plain stores (unique writer,
// after memset). Col partials -> scratch; col_merge_scatter merges 8 chunks,
// exp-reranks, atomicAdds on top.
//
// Top-k exactness: top-4 on RAW scores ordered (v desc, idx asc); 4 finalists
// re-ranked by (expf desc, idx asc); top-3 kept. Matches jax.lax.top_k over
// exp() including float32 exp-rounding ties. Scans ascend in index and
// prefilters use >=, so ties resolve lowest-index-first.
//
// Smem stride S+16 (=272 for S=256): row-scan LDS.128 phases cover one row
// per 8-lane phase (banks 4*sub, conflict-free); col-scan scalar reads are
// consecutive per lane (conflict-free); cp.async STS.128 conflict-free.

#define CH      32
#define NCHUNK  8            // R / CH
#define MAX_PART (1 << 20)   // >= P*NCHUNK*S = 1048576

__device__ float4 g_pv[MAX_PART];
__device__ int4   g_pi[MAX_PART];

struct T4 { float v0, v1, v2, v3; int i0, i1, i2, i3; };

__device__ __forceinline__ bool better(float v, int i, float w, int j) {
    return (v > w) || (v == w && (unsigned)i < (unsigned)j);
}

__device__ __forceinline__ void t4_init(T4& t) {
    t.v0 = t.v1 = t.v2 = t.v3 = -INFINITY;
    t.i0 = t.i1 = t.i2 = t.i3 = 0x7FFFFFFF;
}

__device__ __forceinline__ void t4_insert(T4& t, float v, int i) {
    if (better(v, i, t.v3, t.i3)) {
        if (better(v, i, t.v2, t.i2)) {
            t.v3 = t.v2; t.i3 = t.i2;
            if (better(v, i, t.v1, t.i1)) {
                t.v2 = t.v1; t.i2 = t.i1;
                if (better(v, i, t.v0, t.i0)) {
                    t.v1 = t.v0; t.i1 = t.i0;
                    t.v0 = v; t.i0 = i;
                } else { t.v1 = v; t.i1 = i; }
            } else { t.v2 = v; t.i2 = i; }
        } else { t.v3 = v; t.i3 = i; }
    }
}

// Re-rank 4 raw finalists by (expf desc, idx asc); emit top-3.
__device__ __forceinline__ void finalize3(const T4& t, float* ev, int* ei) {
    float e[4] = { expf(t.v0), expf(t.v1), expf(t.v2), expf(t.v3) };
    int   x[4] = { t.i0, t.i1, t.i2, t.i3 };
    #pragma unroll
    for (int a = 1; a < 4; a++) {
        #pragma unroll
        for (int b = a; b > 0; b--) {
            if (better(e[b], x[b], e[b-1], x[b-1])) {
                float tv = e[b]; e[b] = e[b-1]; e[b-1] = tv;
                int   ti = x[b]; x[b] = x[b-1]; x[b-1] = ti;
            }
        }
    }
    ev[0] = e[0]; ev[1] = e[1]; ev[2] = e[2];
    ei[0] = x[0]; ei[1] = x[1]; ei[2] = x[2];
}

__device__ __forceinline__ void cp_async16(uint32_t smem_dst, const void* gmem_src) {
    asm volatile("cp.async.cg.shared.global [%0], [%1], 16;"
                 :: "r"(smem_dst), "l"(gmem_src));
}
__device__ __forceinline__ void cp_async_wait_all() {
    asm volatile("cp.async.commit_group;\n\tcp.async.wait_group 0;" ::: "memory");
}

// ---------------------------------------------------------------------------
// Fused tile: block = (p, r-chunk of CH). 256 threads. smem CH*(S+16) floats.
// ---------------------------------------------------------------------------
template <typename CorrT>
__global__ void __launch_bounds__(256)
fused_tile(const float* __restrict__ msm,
           const unsigned int* __restrict__ refm,
           const unsigned int* __restrict__ srcm,
           float* __restrict__ score_out,
           CorrT* __restrict__ corr_out,
           int P, int R, int S)
{
    extern __shared__ float tile[];          // [CH][S+16]
    const int stride = S + 16;
    const int bx = blockIdx.x;               // p*NCHUNK + c
    const int c  = bx % NCHUNK;
    const int p  = bx / NCHUNK;
    const int rbase = c * CH;
    const int tid  = threadIdx.x;
    const int lane = tid & 31;
    const int wid  = tid >> 5;

    // ---- load tile: cp.async, 8 independent 16B copies, no staging regs ----
    if (S == 256) {
        const float* __restrict__ srcf = msm + ((size_t)p * R + rbase) * S;
        const int g   = tid & 63;            // float4 column 0..63
        const int rl0 = tid >> 6;            // 0..3
        const uint32_t smem_base = (uint32_t)__cvta_generic_to_shared(tile);
        #pragma unroll
        for (int k = 0; k < 8; k++) {
            const int rl = rl0 + (k << 2);
            cp_async16(smem_base + (uint32_t)((rl * stride + (g << 2)) * 4),
                       srcf + (size_t)rl * 256 + (g << 2));
        }
        cp_async_wait_all();
    } else {
        const float4* __restrict__ src =
            (const float4*)(msm + ((size_t)p * R + rbase) * S);
        const int sq = S >> 2;
        const int nq = CH * sq;
        for (int q = tid; q < nq; q += blockDim.x) {
            const float4 v = __ldg(src + q);
            const int rl = q / sq;
            const int gg = q - rl * sq;
            *((float4*)&tile[rl * stride + (gg << 2)]) = v;
        }
    }
    __syncthreads();

    // ---- row top-k: 8 lanes per row, 4 rows per warp, LDS.128 + prefilter ----
    {
        const int row_local = (wid << 2) + (lane >> 3);   // 0..CH-1
        const int sub = lane & 7;
        const float* __restrict__ rp = &tile[row_local * stride];
        const int nje = (S >> 5);            // float4-groups per lane (8 for S=256)

        T4 t; t4_init(t);
        #pragma unroll 4
        for (int j = 0; j < nje; j++) {
            const int f4i = sub + (j << 3);            // float4 index
            const float4 v = *((const float4*)&rp[f4i << 2]);
            const float mx = fmaxf(fmaxf(v.x, v.y), fmaxf(v.z, v.w));
            if (mx >= t.v3) {
                const int s0 = f4i << 2;
                t4_insert(t, v.x, s0);
                t4_insert(t, v.y, s0 + 1);
                t4_insert(t, v.z, s0 + 2);
                t4_insert(t, v.w, s0 + 3);
            }
        }
        // merge across the 8-lane group (disjoint index sets)
        #pragma unroll
        for (int off = 1; off <= 4; off <<= 1) {
            float v0 = __shfl_xor_sync(0xFFFFFFFFu, t.v0, off);
            float v1 = __shfl_xor_sync(0xFFFFFFFFu, t.v1, off);
            float v2 = __shfl_xor_sync(0xFFFFFFFFu, t.v2, off);
            float v3 = __shfl_xor_sync(0xFFFFFFFFu, t.v3, off);
            int   i0 = __shfl_xor_sync(0xFFFFFFFFu, t.i0, off);
            int   i1 = __shfl_xor_sync(0xFFFFFFFFu, t.i1, off);
            int   i2 = __shfl_xor_sync(0xFFFFFFFFu, t.i2, off);
            int   i3 = __shfl_xor_sync(0xFFFFFFFFu, t.i3, off);
            t4_insert(t, v0, i0);
            t4_insert(t, v1, i1);
            t4_insert(t, v2, i2);
            t4_insert(t, v3, i3);
        }

        if (sub == 0) {
            float ev[3]; int ei[3];
            finalize3(t, ev, ei);
            const int rowg = p * R + rbase + row_local;   // global (p,r) id
            const bool rm = __ldg(refm + rowg) != 0u;
            #pragma unroll
            for (int k = 0; k < 3; k++) {
                const int s = ei[k];
                if ((unsigned)s < (unsigned)S) {
                    score_out[(size_t)rowg * S + s] = 0.5f * ev[k];
                    if (rm && __ldg(srcm + (size_t)p * S + s) != 0u) {
                        corr_out[(size_t)rowg * S + s] = (CorrT)1;
                    }
                }
            }
        }
    }

    // ---- col partial top-4: thread per column, 4-row groups + prefilter ----
    {
        const int s = tid;                   // blockDim.x == S assumed (256)
        T4 t; t4_init(t);
        #pragma unroll 4
        for (int g = 0; g < (CH >> 2); g++) {
            const int r0 = g << 2;
            const float f0 = tile[(r0 + 0) * stride + s];
            const float f1 = tile[(r0 + 1) * stride + s];
            const float f2 = tile[(r0 + 2) * stride + s];
            const float f3 = tile[(r0 + 3) * stride + s];
            const float mx = fmaxf(fmaxf(f0, f1), fmaxf(f2, f3));
            if (mx >= t.v3) {
                t4_insert(t, f0, rbase + r0);
                t4_insert(t, f1, rbase + r0 + 1);
                t4_insert(t, f2, rbase + r0 + 2);
                t4_insert(t, f3, rbase + r0 + 3);
            }
        }
        const int q = bx * S + s;
        g_pv[q] = make_float4(t.v0, t.v1, t.v2, t.v3);
        g_pi[q] = make_int4(t.i0, t.i1, t.i2, t.i3);
    }
}

// ---------------------------------------------------------------------------
// Col merge + scatter: thread per (p,s). Coalesced scratch reads, atomicAdd
// on top of the fused kernel's row stores.
// ---------------------------------------------------------------------------
template <typename CorrT>
__global__ void col_merge_scatter(const unsigned int* __restrict__ refm,
                                  const unsigned int* __restrict__ srcm,
                                  float* __restrict__ score_out,
                                  CorrT* __restrict__ corr_out,
                                  int P, int R, int S)
{
    const int idx = (int)(blockIdx.x * (size_t)blockDim.x + threadIdx.x);
    if (idx >= P * S) return;
    const int p = idx / S;
    const int s = idx - p * S;

    T4 t; t4_init(t);
    #pragma unroll
    for (int c = 0; c < NCHUNK; c++) {
        const int q = (p * NCHUNK + c) * S + s;
        const float4 v = g_pv[q];
        const int4   i = g_pi[q];
        t4_insert(t, v.x, i.x);
        t4_insert(t, v.y, i.y);
        t4_insert(t, v.z, i.z);
        t4_insert(t, v.w, i.w);
    }

    float ev[3]; int ei[3];
    finalize3(t, ev, ei);
    const bool sm = __ldg(srcm + idx) != 0u;
    #pragma unroll
    for (int q = 0; q < 3; q++) {
        const int r = ei[q];
        if ((unsigned)r < (unsigned)R) {
            atomicAdd(&score_out[((size_t)p * R + r) * S + s], 0.5f * ev[q]);
            if (sm && __ldg(refm + (size_t)p * R + r) != 0u) {
                corr_out[((size_t)p * R + r) * S + s] = (CorrT)1;
            }
        }
    }
}

extern "C" void kernel_launch(void* const* d_in, const int* in_sizes, int n_in,
                              void* d_out, int out_size)
{
    const float*        msm  = (const float*)d_in[0];
    // d_in[1] = node_corr_scores (unused: conditional=False)
    const unsigned int* refm = (const unsigned int*)d_in[2];   // bool -> 4-byte
    const unsigned int* srcm = (const unsigned int*)d_in[3];   // bool -> 4-byte

    const int P = in_sizes[1];
    const int R = in_sizes[2] / P;
    const int S = in_sizes[3] / P;
    const size_t N = (size_t)P * R * S;

    float* score_out = (float*)d_out;

    const int fused_blocks = P * NCHUNK;            // R/CH chunks per p
    const int fused_tpb = 256;                      // == S
    const size_t smem = (size_t)CH * (S + 16) * sizeof(float);
    const int mrg_tpb = 256;
    const int mrg_blocks = (P * S + mrg_tpb - 1) / mrg_tpb;

    if ((size_t)out_size == 2 * N) {
        // [score_map (f32) | corr_map (f32)]
        cudaFuncSetAttribute(fused_tile<float>,
                             cudaFuncAttributeMaxDynamicSharedMemorySize,
                             (int)smem);
        cudaMemsetAsync(d_out, 0, 2 * N * sizeof(float), 0);
        float* corr_out = score_out + N;
        fused_tile<float><<<fused_blocks, fused_tpb, smem>>>(
            msm, refm, srcm, score_out, corr_out, P, R, S);
        col_merge_scatter<float><<<mrg_blocks, mrg_tpb>>>(
            refm, srcm, score_out, corr_out, P, R, S);
    } else {
        // [score_map (f32) | corr_map (u8)]
        cudaFuncSetAttribute(fused_tile<unsigned char>,
                             cudaFuncAttributeMaxDynamicSharedMemorySize,
                             (int)smem);
        cudaMemsetAsync(d_out, 0, N * sizeof(float) + N, 0);
        unsigned char* corr_out = (unsigned char*)d_out + N * sizeof(float);
        fused_tile<unsigned char><<<fused_blocks, fused_tpb, smem>>>(
            msm, refm, srcm, score_out, corr_out, P, R, S);
        col_merge_scatter<unsigned char><<<mrg_blocks, mrg_tpb>>>(
            refm, srcm, score_out, corr_out, P, R, S);
    }
}

// round 13
// speedup vs baseline: 1.3151x; 1.3151x over previous
#include <cuda_runtime.h>
#include <math.h>

// InstanceAwarePointMatching — memset + two high-MLP streaming passes.
//   score = exp(msm) [P,R,S]; row top-3 along s; col top-3 along r.
//   score_map = 0.5*(ref+src); corr_map = (row_hit|col_hit) & refm & srcm.
// Masks arrive as 4-byte elements (uint32 != 0).
//
// KEY STRUCTURE (learned R7-R12): never put a data-dependent branch between
// loads. Each loop iteration does a branch-free batch of independent loads +
// an FMAX tree, then ONE prefilter branch on the batch max. ptxas front-
// batches the loads -> MLP 8-16 -> latency hidden, DRAM-rate streaming.
//
// Top-k exactness: top-4 on RAW scores ordered (v desc, idx asc); 4 finalists
// re-ranked by (expf desc, idx asc); top-3 kept. Matches jax.lax.top_k over
// exp() including float32 exp-rounding ties. Scans ascend in index; stored
// entries always have smaller index than candidates, so the >= prefilter and
// tie-break are exact.
//
// Write protocol (stream-serialized): memset zeros both maps; row kernel
// plain-stores (unique writer per (p,r,s)); col kernel atomicAdds score on
// top and stores corr=1 (same value as any row store -> benign).

struct T4 { float v0, v1, v2, v3; int i0, i1, i2, i3; };

__device__ __forceinline__ bool better(float v, int i, float w, int j) {
    return (v > w) || (v == w && (unsigned)i < (unsigned)j);
}

__device__ __forceinline__ void t4_init(T4& t) {
    t.v0 = t.v1 = t.v2 = t.v3 = -INFINITY;
    t.i0 = t.i1 = t.i2 = t.i3 = 0x7FFFFFFF;
}

__device__ __forceinline__ void t4_insert(T4& t, float v, int i) {
    if (better(v, i, t.v3, t.i3)) {
        if (better(v, i, t.v2, t.i2)) {
            t.v3 = t.v2; t.i3 = t.i2;
            if (better(v, i, t.v1, t.i1)) {
                t.v2 = t.v1; t.i2 = t.i1;
                if (better(v, i, t.v0, t.i0)) {
                    t.v1 = t.v0; t.i1 = t.i0;
                    t.v0 = v; t.i0 = i;
                } else { t.v1 = v; t.i1 = i; }
            } else { t.v2 = v; t.i2 = i; }
        } else { t.v3 = v; t.i3 = i; }
    }
}

// Re-rank 4 raw finalists by (expf desc, idx asc); emit top-3.
__device__ __forceinline__ void finalize3(const T4& t, float* ev, int* ei) {
    float e[4] = { expf(t.v0), expf(t.v1), expf(t.v2), expf(t.v3) };
    int   x[4] = { t.i0, t.i1, t.i2, t.i3 };
    #pragma unroll
    for (int a = 1; a < 4; a++) {
        #pragma unroll
        for (int b = a; b > 0; b--) {
            if (better(e[b], x[b], e[b-1], x[b-1])) {
                float tv = e[b]; e[b] = e[b-1]; e[b-1] = tv;
                int   ti = x[b]; x[b] = x[b-1]; x[b-1] = ti;
            }
        }
    }
    ev[0] = e[0]; ev[1] = e[1]; ev[2] = e[2];
    ei[0] = x[0]; ei[1] = x[1]; ei[2] = x[2];
}

// ---------------------------------------------------------------------------
// Row pass: ONE THREAD per (p,r). Batches of 4 independent float4 loads
// (16 elements), FMAX tree, single prefilter branch. L1 line reuse across
// the thread's consecutive float4s keeps effective latency low.
// ---------------------------------------------------------------------------
template <typename CorrT>
__global__ void __launch_bounds__(256)
row_topk_scatter(const float* __restrict__ msm,
                 const unsigned int* __restrict__ refm,
                 const unsigned int* __restrict__ srcm,
                 float* __restrict__ score_out,
                 CorrT* __restrict__ corr_out,
                 int P, int R, int S)
{
    const int row = (int)(blockIdx.x * (size_t)blockDim.x + threadIdx.x);
    if (row >= P * R) return;
    const int p = row / R;

    const float4* __restrict__ rowp = (const float4*)(msm + (size_t)row * S);
    const int nj = S >> 2;                 // float4s per row

    T4 t; t4_init(t);
    int j = 0;
    for (; j + 4 <= nj; j += 4) {
        // 4 independent loads, no branch in between
        const float4 a = __ldg(rowp + j);
        const float4 b = __ldg(rowp + j + 1);
        const float4 c = __ldg(rowp + j + 2);
        const float4 d = __ldg(rowp + j + 3);
        const float m0 = fmaxf(fmaxf(a.x, a.y), fmaxf(a.z, a.w));
        const float m1 = fmaxf(fmaxf(b.x, b.y), fmaxf(b.z, b.w));
        const float m2 = fmaxf(fmaxf(c.x, c.y), fmaxf(c.z, c.w));
        const float m3 = fmaxf(fmaxf(d.x, d.y), fmaxf(d.z, d.w));
        const float mx = fmaxf(fmaxf(m0, m1), fmaxf(m2, m3));
        if (mx >= t.v3) {
            const int s0 = j << 2;
            t4_insert(t, a.x, s0);      t4_insert(t, a.y, s0 + 1);
            t4_insert(t, a.z, s0 + 2);  t4_insert(t, a.w, s0 + 3);
            t4_insert(t, b.x, s0 + 4);  t4_insert(t, b.y, s0 + 5);
            t4_insert(t, b.z, s0 + 6);  t4_insert(t, b.w, s0 + 7);
            t4_insert(t, c.x, s0 + 8);  t4_insert(t, c.y, s0 + 9);
            t4_insert(t, c.z, s0 + 10); t4_insert(t, c.w, s0 + 11);
            t4_insert(t, d.x, s0 + 12); t4_insert(t, d.y, s0 + 13);
            t4_insert(t, d.z, s0 + 14); t4_insert(t, d.w, s0 + 15);
        }
    }
    for (; j < nj; j++) {                  // remainder (unused for S=256)
        const float4 a = __ldg(rowp + j);
        const int s0 = j << 2;
        t4_insert(t, a.x, s0);     t4_insert(t, a.y, s0 + 1);
        t4_insert(t, a.z, s0 + 2); t4_insert(t, a.w, s0 + 3);
    }

    float ev[3]; int ei[3];
    finalize3(t, ev, ei);
    const bool rm = __ldg(refm + row) != 0u;
    #pragma unroll
    for (int k = 0; k < 3; k++) {
        const int s = ei[k];
        if ((unsigned)s < (unsigned)S) {
            score_out[(size_t)row * S + s] = 0.5f * ev[k];
            if (rm && __ldg(srcm + (size_t)p * S + s) != 0u) {
                corr_out[(size_t)row * S + s] = (CorrT)1;
            }
        }
    }
}

// ---------------------------------------------------------------------------
// Col pass: ONE THREAD per (p,s), full column (no merge needed). Batches of
// 8 independent coalesced scalar loads (warp reads 8 full 128B lines per
// batch), FMAX tree, single prefilter branch.
// ---------------------------------------------------------------------------
template <typename CorrT>
__global__ void __launch_bounds__(256)
col_topk_scatter(const float* __restrict__ msm,
                 const unsigned int* __restrict__ refm,
                 const unsigned int* __restrict__ srcm,
                 float* __restrict__ score_out,
                 CorrT* __restrict__ corr_out,
                 int P, int R, int S)
{
    const int idx = (int)(blockIdx.x * (size_t)blockDim.x + threadIdx.x);
    if (idx >= P * S) return;
    const int p = idx / S;
    const int s = idx - p * S;

    const float* __restrict__ base = msm + (size_t)p * R * S + s;

    T4 t; t4_init(t);
    int r0 = 0;
    for (; r0 + 8 <= R; r0 += 8) {
        float v[8];
        #pragma unroll
        for (int k = 0; k < 8; k++) {
            v[k] = __ldg(base + (size_t)(r0 + k) * S);
        }
        const float m0 = fmaxf(fmaxf(v[0], v[1]), fmaxf(v[2], v[3]));
        const float m1 = fmaxf(fmaxf(v[4], v[5]), fmaxf(v[6], v[7]));
        const float mx = fmaxf(m0, m1);
        if (mx >= t.v3) {
            #pragma unroll
            for (int k = 0; k < 8; k++) {
                t4_insert(t, v[k], r0 + k);
            }
        }
    }
    for (; r0 < R; r0++) {                 // remainder (unused for R=256)
        t4_insert(t, __ldg(base + (size_t)r0 * S), r0);
    }

    float ev[3]; int ei[3];
    finalize3(t, ev, ei);
    const bool sm = __ldg(srcm + idx) != 0u;
    #pragma unroll
    for (int k = 0; k < 3; k++) {
        const int r = ei[k];
        if ((unsigned)r < (unsigned)R) {
            atomicAdd(&score_out[((size_t)p * R + r) * S + s], 0.5f * ev[k]);
            if (sm && __ldg(refm + (size_t)p * R + r) != 0u) {
                corr_out[((size_t)p * R + r) * S + s] = (CorrT)1;
            }
        }
    }
}

extern "C" void kernel_launch(void* const* d_in, const int* in_sizes, int n_in,
                              void* d_out, int out_size)
{
    const float*        msm  = (const float*)d_in[0];
    // d_in[1] = node_corr_scores (unused: conditional=False)
    const unsigned int* refm = (const unsigned int*)d_in[2];   // bool -> 4-byte
    const unsigned int* srcm = (const unsigned int*)d_in[3];   // bool -> 4-byte

    const int P = in_sizes[1];
    const int R = in_sizes[2] / P;
    const int S = in_sizes[3] / P;
    const size_t N = (size_t)P * R * S;

    float* score_out = (float*)d_out;
    const int tpb = 256;
    const int row_blocks = (P * R + tpb - 1) / tpb;
    const int col_blocks = (P * S + tpb - 1) / tpb;

    if ((size_t)out_size == 2 * N) {
        // [score_map (f32) | corr_map (f32)]
        cudaMemsetAsync(d_out, 0, 2 * N * sizeof(float), 0);
        float* corr_out = score_out + N;
        row_topk_scatter<float><<<row_blocks, tpb>>>(
            msm, refm, srcm, score_out, corr_out, P, R, S);
        col_topk_scatter<float><<<col_blocks, tpb>>>(
            msm, refm, srcm, score_out, corr_out, P, R, S);
    } else {
        // [score_map (f32) | corr_map (u8)]
        cudaMemsetAsync(d_out, 0, N * sizeof(float) + N, 0);
        unsigned char* corr_out = (unsigned char*)d_out + N * sizeof(float);
        row_topk_scatter<unsigned char><<<row_blocks, tpb>>>(
            msm, refm, srcm, score_out, corr_out, P, R, S);
        col_topk_scatter<unsigned char><<<col_blocks, tpb>>>(
            msm, refm, srcm, score_out, corr_out, P, R, S);
    }
}

// round 14
// speedup vs baseline: 1.4612x; 1.1110x over previous
#include <cuda_runtime.h>
#include <math.h>

// InstanceAwarePointMatching — memset + ONE dual kernel (row blocks + col blocks).
//   score = exp(msm) [P,R,S]; row top-3 along s; col top-3 along r.
//   score_map = 0.5*(ref+src); corr_map = (row_hit|col_hit) & refm & srcm.
// Masks arrive as 4-byte elements (uint32 != 0).
//
// R13 lesson kept: branch-free batches of independent loads + FMAX tree, ONE
// prefilter branch per batch -> MLP 8-16, latency hidden.
// R14 change: row and col passes run CONCURRENTLY in one launch (blocks
// 0..rowB-1 = row path, rest = col path). Doubles resident warps (occ ~86%),
// aggregates DRAM demand, and gets L2 reuse (input ~fits in 126MB L2).
// Both paths scatter score via atomicAdd (order-independent); corr stores of
// 1.0f race benignly.
//
// Top-k exactness: top-4 on RAW scores ordered (v desc, idx asc); 4 finalists
// re-ranked by (expf desc, idx asc); top-3 kept. Matches jax.lax.top_k over
// exp() including float32 exp-rounding ties. Scans ascend in index; stored
// entries always have smaller index than later candidates, so >= prefilters
// and tie-breaks are exact.

struct T4 { float v0, v1, v2, v3; int i0, i1, i2, i3; };

__device__ __forceinline__ bool better(float v, int i, float w, int j) {
    return (v > w) || (v == w && (unsigned)i < (unsigned)j);
}

__device__ __forceinline__ void t4_init(T4& t) {
    t.v0 = t.v1 = t.v2 = t.v3 = -INFINITY;
    t.i0 = t.i1 = t.i2 = t.i3 = 0x7FFFFFFF;
}

__device__ __forceinline__ void t4_insert(T4& t, float v, int i) {
    if (better(v, i, t.v3, t.i3)) {
        if (better(v, i, t.v2, t.i2)) {
            t.v3 = t.v2; t.i3 = t.i2;
            if (better(v, i, t.v1, t.i1)) {
                t.v2 = t.v1; t.i2 = t.i1;
                if (better(v, i, t.v0, t.i0)) {
                    t.v1 = t.v0; t.i1 = t.i0;
                    t.v0 = v; t.i0 = i;
                } else { t.v1 = v; t.i1 = i; }
            } else { t.v2 = v; t.i2 = i; }
        } else { t.v3 = v; t.i3 = i; }
    }
}

// Re-rank 4 raw finalists by (expf desc, idx asc); emit top-3.
__device__ __forceinline__ void finalize3(const T4& t, float* ev, int* ei) {
    float e[4] = { expf(t.v0), expf(t.v1), expf(t.v2), expf(t.v3) };
    int   x[4] = { t.i0, t.i1, t.i2, t.i3 };
    #pragma unroll
    for (int a = 1; a < 4; a++) {
        #pragma unroll
        for (int b = a; b > 0; b--) {
            if (better(e[b], x[b], e[b-1], x[b-1])) {
                float tv = e[b]; e[b] = e[b-1]; e[b-1] = tv;
                int   ti = x[b]; x[b] = x[b-1]; x[b-1] = ti;
            }
        }
    }
    ev[0] = e[0]; ev[1] = e[1]; ev[2] = e[2];
    ei[0] = x[0]; ei[1] = x[1]; ei[2] = x[2];
}

// ---------------------------------------------------------------------------
// Dual kernel: blocks [0, rowB) = row path (thread per (p,r), float4 batches);
// blocks [rowB, rowB+colB) = col path (thread per (p,s), coalesced batches).
// Both paths: atomicAdd score, plain-store corr=1.
// ---------------------------------------------------------------------------
template <typename CorrT>
__global__ void __launch_bounds__(256)
dual_topk_scatter(const float* __restrict__ msm,
                  const unsigned int* __restrict__ refm,
                  const unsigned int* __restrict__ srcm,
                  float* __restrict__ score_out,
                  CorrT* __restrict__ corr_out,
                  int P, int R, int S, int rowB)
{
    if ((int)blockIdx.x < rowB) {
        // ================= ROW PATH =================
        const int row = (int)(blockIdx.x * blockDim.x + threadIdx.x);
        if (row >= P * R) return;
        const int p = row / R;

        const float4* __restrict__ rowp = (const float4*)(msm + (size_t)row * S);
        const int nj = S >> 2;

        T4 t; t4_init(t);
        int j = 0;
        for (; j + 4 <= nj; j += 4) {
            const float4 a = __ldg(rowp + j);
            const float4 b = __ldg(rowp + j + 1);
            const float4 c = __ldg(rowp + j + 2);
            const float4 d = __ldg(rowp + j + 3);
            const float m0 = fmaxf(fmaxf(a.x, a.y), fmaxf(a.z, a.w));
            const float m1 = fmaxf(fmaxf(b.x, b.y), fmaxf(b.z, b.w));
            const float m2 = fmaxf(fmaxf(c.x, c.y), fmaxf(c.z, c.w));
            const float m3 = fmaxf(fmaxf(d.x, d.y), fmaxf(d.z, d.w));
            const float mx = fmaxf(fmaxf(m0, m1), fmaxf(m2, m3));
            if (mx >= t.v3) {
                const int s0 = j << 2;
                t4_insert(t, a.x, s0);      t4_insert(t, a.y, s0 + 1);
                t4_insert(t, a.z, s0 + 2);  t4_insert(t, a.w, s0 + 3);
                t4_insert(t, b.x, s0 + 4);  t4_insert(t, b.y, s0 + 5);
                t4_insert(t, b.z, s0 + 6);  t4_insert(t, b.w, s0 + 7);
                t4_insert(t, c.x, s0 + 8);  t4_insert(t, c.y, s0 + 9);
                t4_insert(t, c.z, s0 + 10); t4_insert(t, c.w, s0 + 11);
                t4_insert(t, d.x, s0 + 12); t4_insert(t, d.y, s0 + 13);
                t4_insert(t, d.z, s0 + 14); t4_insert(t, d.w, s0 + 15);
            }
        }
        for (; j < nj; j++) {
            const float4 a = __ldg(rowp + j);
            const int s0 = j << 2;
            t4_insert(t, a.x, s0);     t4_insert(t, a.y, s0 + 1);
            t4_insert(t, a.z, s0 + 2); t4_insert(t, a.w, s0 + 3);
        }

        float ev[3]; int ei[3];
        finalize3(t, ev, ei);
        const bool rm = __ldg(refm + row) != 0u;
        #pragma unroll
        for (int k = 0; k < 3; k++) {
            const int s = ei[k];
            if ((unsigned)s < (unsigned)S) {
                atomicAdd(&score_out[(size_t)row * S + s], 0.5f * ev[k]);
                if (rm && __ldg(srcm + (size_t)p * S + s) != 0u) {
                    corr_out[(size_t)row * S + s] = (CorrT)1;
                }
            }
        }
    } else {
        // ================= COL PATH =================
        const int idx = (int)((blockIdx.x - rowB) * blockDim.x + threadIdx.x);
        if (idx >= P * S) return;
        const int p = idx / S;
        const int s = idx - p * S;

        const float* __restrict__ base = msm + (size_t)p * R * S + s;

        T4 t; t4_init(t);
        int r0 = 0;
        for (; r0 + 8 <= R; r0 += 8) {
            float v[8];
            #pragma unroll
            for (int k = 0; k < 8; k++) {
                v[k] = __ldg(base + (size_t)(r0 + k) * S);
            }
            const float m0 = fmaxf(fmaxf(v[0], v[1]), fmaxf(v[2], v[3]));
            const float m1 = fmaxf(fmaxf(v[4], v[5]), fmaxf(v[6], v[7]));
            const float mx = fmaxf(m0, m1);
            if (mx >= t.v3) {
                #pragma unroll
                for (int k = 0; k < 8; k++) {
                    t4_insert(t, v[k], r0 + k);
                }
            }
        }
        for (; r0 < R; r0++) {
            t4_insert(t, __ldg(base + (size_t)r0 * S), r0);
        }

        float ev[3]; int ei[3];
        finalize3(t, ev, ei);
        const bool sm = __ldg(srcm + idx) != 0u;
        #pragma unroll
        for (int k = 0; k < 3; k++) {
            const int r = ei[k];
            if ((unsigned)r < (unsigned)R) {
                atomicAdd(&score_out[((size_t)p * R + r) * S + s], 0.5f * ev[k]);
                if (sm && __ldg(refm + (size_t)p * R + r) != 0u) {
                    corr_out[((size_t)p * R + r) * S + s] = (CorrT)1;
                }
            }
        }
    }
}

extern "C" void kernel_launch(void* const* d_in, const int* in_sizes, int n_in,
                              void* d_out, int out_size)
{
    const float*        msm  = (const float*)d_in[0];
    // d_in[1] = node_corr_scores (unused: conditional=False)
    const unsigned int* refm = (const unsigned int*)d_in[2];   // bool -> 4-byte
    const unsigned int* srcm = (const unsigned int*)d_in[3];   // bool -> 4-byte

    const int P = in_sizes[1];
    const int R = in_sizes[2] / P;
    const int S = in_sizes[3] / P;
    const size_t N = (size_t)P * R * S;

    float* score_out = (float*)d_out;
    const int tpb = 256;
    const int rowB = (P * R + tpb - 1) / tpb;
    const int colB = (P * S + tpb - 1) / tpb;

    if ((size_t)out_size == 2 * N) {
        // [score_map (f32) | corr_map (f32)]
        cudaMemsetAsync(d_out, 0, 2 * N * sizeof(float), 0);
        float* corr_out = score_out + N;
        dual_topk_scatter<float><<<rowB + colB, tpb>>>(
            msm, refm, srcm, score_out, corr_out, P, R, S, rowB);
    } else {
        // [score_map (f32) | corr_map (u8)]
        cudaMemsetAsync(d_out, 0, N * sizeof(float) + N, 0);
        unsigned char* corr_out = (unsigned char*)d_out + N * sizeof(float);
        dual_topk_scatter<unsigned char><<<rowB + colB, tpb>>>(
            msm, refm, srcm, score_out, corr_out, P, R, S, rowB);
    }
}